// round 10
// baseline (speedup 1.0000x reference)
#include <cuda_runtime.h>
#include <math.h>

#define NP 512
#define ND 3
#define NK 32
#define NT 10
#define NB 8
#define EPSF 1e-6f

#define NTAB 1024
#define DRANGE 4.0f
#define TSCALE ((float)NTAB / DRANGE)

#define IPB 16                           // target i's per block
#define PTPB (IPB * 32)                  // 512 threads
#define PAIR_BLOCKS (NB * (NP / IPB))    // 256 blocks

__device__ float4   g_qtab[NTAB];        // (fm_i, dfm_i, fm_{i+1}-fm_i, dfm_{i+1}-dfm_i)
__device__ float    g_divpart[NB * NP];
__device__ unsigned g_count = 0;

// ---- launch 1: 8 blocks x 128 thr; one grid point per thread ----
__global__ void __launch_bounds__(128) build_table_kernel(
    const float* __restrict__ t_in,
    const float* __restrict__ mus,
    const float* __restrict__ nlg,
    const float* __restrict__ mus_t,
    const float* __restrict__ nlg_t,
    const float* __restrict__ W,
    const float* __restrict__ bias,
    const float* __restrict__ imp)
{
    __shared__ float s_mu[NK], s_ig2[NK], s_w[NK];
    __shared__ float s_cadd;

    const int tid = threadIdx.x;

    if (tid < NK) {
        const int k = tid;
        const float t = t_in[0];
        float tr[NT];
        float ssum = 0.f;
#pragma unroll
        for (int q = 0; q < NT; q++) {
            float ig = __expf(nlg_t[q]);
            float df = t - mus_t[q];
            float v  = __expf(-df * df * ig * ig);
            tr[q] = v;
            ssum += v;
        }
        const float invs = 1.0f / (EPSF + ssum);

        float w = 0.f;
#pragma unroll
        for (int q = 0; q < NT; q++) w = fmaf(W[k * NT + q], tr[q], w);
        w *= invs;

        float v = imp[k] * imp[k] * w;
#pragma unroll
        for (int o = 16; o; o >>= 1) v += __shfl_down_sync(0xffffffffu, v, o);

        float ig = __expf(nlg[k]);
        s_mu[k]  = mus[k];
        s_ig2[k] = ig * ig;
        s_w[k]   = w;
        if (k == 0) {
            float cadd = v;
#pragma unroll
            for (int q = 0; q < NT; q++) cadd = fmaf(bias[q] * invs, tr[q], cadd);
            s_cadd = cadd;
        }
    }
    __syncthreads();

    const float cadd = s_cadd;
    const int idx = blockIdx.x * 128 + tid;   // 0..1023

    // evaluate (fm, dfm) at this grid point (and implicitly serve as the
    // neighbor's "+1" sample by writing slope slots of entry idx-1)
    const float d = (float)idx * (DRANGE / (float)NTAB);
    float S0 = 0.f, W0 = 0.f, SD = 0.f, SDW = 0.f;
#pragma unroll 8
    for (int k = 0; k < NK; k++) {
        float diff = d - s_mu[k];
        float ig2  = s_ig2[k];
        float r  = __expf(-diff * diff * ig2);
        float dr = -2.f * diff * ig2 * r;
        S0  += r;
        W0   = fmaf(r,  s_w[k], W0);
        SD  += dr;
        SDW  = fmaf(dr, s_w[k], SDW);
    }
    const float inv = 1.0f / (EPSF + S0);
    const float fm  = fmaf(W0, inv, cadd);
    const float dfm = (SDW - W0 * SD * inv) * inv;

    // exchange with neighbor thread to build slope-form quads without a second pass
    const float fm_up  = __shfl_down_sync(0xffffffffu, fm, 1);
    const float dfm_up = __shfl_down_sync(0xffffffffu, dfm, 1);

    float* gt = (float*)g_qtab;
    if ((tid & 31) < 31) {
        // full quad for idx
        float4 q;
        q.x = fm; q.y = dfm; q.z = fm_up - fm; q.w = dfm_up - dfm;
        g_qtab[idx] = q;
    } else {
        // lane 31: write own base; its slope written by cross-warp neighbor below
        gt[4 * idx + 0] = fm;
        gt[4 * idx + 1] = dfm;
        if (idx == NTAB - 1) {            // asymptotic flat tail
            gt[4 * idx + 2] = 0.f;
            gt[4 * idx + 3] = 0.f;
        }
    }
    if ((tid & 31) == 0 && idx > 0) {
        // serve as the +1 sample for entry idx-1 (cross-warp boundary)
        // slope = fm(idx) - fm(idx-1): need previous value -> recompute cheaply? no:
        // instead store negative-side: entry idx-1 slope slots
        // fm(idx-1) is unknown here; handled by writing absolute sample and fixing:
        // simpler: entry idx-1's owner (lane 31 of prev warp) lacked fm_up; we write
        // (fm_here - base) using a global read-after? Avoid: store raw fm_here and
        // let a tiny fixup below convert. To stay single-pass we instead store
        // fm_here into slope slot and mark: slope = fm_here - base done by reader?
        // Cleanest: lane 0 writes fm/dfm into PREV quad's zw as ABSOLUTE, then
        // one fixup warp converts the 31-boundary entries after a grid sync — too
        // heavy. Use atomic-free trick: recompute prev point here (cheap, 32 exps).
        const float dprev = (float)(idx - 1) * (DRANGE / (float)NTAB);
        float pS0 = 0.f, pW0 = 0.f, pSD = 0.f, pSDW = 0.f;
#pragma unroll 8
        for (int k = 0; k < NK; k++) {
            float diff = dprev - s_mu[k];
            float ig2  = s_ig2[k];
            float r  = __expf(-diff * diff * ig2);
            float dr = -2.f * diff * ig2 * r;
            pS0  += r;
            pW0   = fmaf(r,  s_w[k], pW0);
            pSD  += dr;
            pSDW  = fmaf(dr, s_w[k], pSDW);
        }
        const float pinv = 1.0f / (EPSF + pS0);
        const float pfm  = fmaf(pW0, pinv, cadd);
        const float pdfm = (pSDW - pW0 * pSD * pinv) * pinv;
        gt[4 * (idx - 1) + 2] = fm - pfm;
        gt[4 * (idx - 1) + 3] = dfm - pdfm;
    }
}

// ---- launch 2: pair kernel. 256 blocks x 512 thr; warp w = target i ----
__global__ void __launch_bounds__(PTPB) pair_kernel(const float* __restrict__ x,
                                                    float* __restrict__ out)
{
    __shared__ float4 s_tab[NTAB];    // 16 KB
    __shared__ float4 s_pos[NP];      // 8 KB
    __shared__ int    s_last;

    const int tid   = threadIdx.x;
    const int bid   = blockIdx.x;
    const int b     = bid >> 5;               // batch (bid / 32)
    const int ibase = (bid & 31) * IPB;       // i-chunk of 16
    const int warp  = tid >> 5;
    const int lane  = tid & 31;

    // fill table: 1024 entries / 512 threads
    {
        const float4* gt = g_qtab;
#pragma unroll
        for (int q = 0; q < NTAB / PTPB; q++)
            s_tab[q * PTPB + tid] = __ldg(&gt[q * PTPB + tid]);
    }
    // fill positions (512 threads, one particle each), padded to float4
    {
        const float* xb = x + b * (NP * ND) + tid * 3;
        float4 p;
        p.x = xb[0]; p.y = xb[1]; p.z = xb[2]; p.w = 0.f;
        s_pos[tid] = p;
    }
    __syncthreads();

    const int i = ibase + warp;
    const float4 pi = s_pos[i];

    float fx = 0.f, fy = 0.f, fz = 0.f, dv = 0.f;

#pragma unroll 4
    for (int it = 0; it < NP / 32; it++) {
        const int j = it * 32 + lane;
        const float4 pj = s_pos[j];
        const float rx = pi.x - pj.x;
        const float ry = pi.y - pj.y;
        const float rz = pi.z - pj.z;
        float d2s = fmaf(rx, rx, fmaf(ry, ry, fmaf(rz, rz, EPSF)));
        float d;
        asm("sqrt.approx.ftz.f32 %0, %1;" : "=f"(d) : "f"(d2s));

        float u = d * TSCALE;
        int i0 = (int)u;
        i0 = min(i0, NTAB - 1);
        float frac = u - (float)i0;
        const float4 q = s_tab[i0];
        float fm  = fmaf(frac, q.z, q.x);
        float dfm = fmaf(frac, q.w, q.y);

        if (j == i) { fm = 0.f; dfm = 0.f; }   // remove_diagonal

        fx = fmaf(rx, fm, fx);
        fy = fmaf(ry, fm, fy);
        fz = fmaf(rz, fm, fz);
        dv += fmaf(d, dfm, 3.f * fm);
    }

    // warp-level reduction only
    const unsigned m = 0xffffffffu;
#pragma unroll
    for (int o = 16; o; o >>= 1) {
        fx += __shfl_down_sync(m, fx, o);
        fy += __shfl_down_sync(m, fy, o);
        fz += __shfl_down_sync(m, fz, o);
        dv += __shfl_down_sync(m, dv, o);
    }
    if (lane == 0) {
        float* fo = out + b * (NP * ND) + i * 3;
        fo[0] = fx; fo[1] = fy; fo[2] = fz;
        g_divpart[b * NP + i] = dv;
        __threadfence();
    }
    __syncthreads();

    if (tid == 0) {
        unsigned old = atomicInc(&g_count, PAIR_BLOCKS - 1);
        s_last = (old == PAIR_BLOCKS - 1) ? 1 : 0;
    }
    __syncthreads();

    // ---- last block: deterministic divergence reduction ----
    if (s_last) {
        __threadfence();
        if (tid < 256) {
            const int bb = tid >> 5;   // warp -> batch (8 warps)
            const int l  = tid & 31;
            float v = 0.f;
#pragma unroll
            for (int c = 0; c < 16; c++)
                v += __ldcg(&g_divpart[bb * NP + l * 16 + c]);
#pragma unroll
            for (int o = 16; o; o >>= 1) v += __shfl_down_sync(m, v, o);
            if (l == 0) out[NB * NP * ND + bb] = -v;
        }
    }
}

extern "C" void kernel_launch(void* const* d_in, const int* in_sizes, int n_in,
                              void* d_out, int out_size)
{
    const float* t_in  = (const float*)d_in[0];
    const float* x     = (const float*)d_in[1];
    const float* mus   = (const float*)d_in[2];
    const float* nlg   = (const float*)d_in[3];
    const float* mus_t = (const float*)d_in[4];
    const float* nlg_t = (const float*)d_in[5];
    const float* W     = (const float*)d_in[6];
    const float* bias  = (const float*)d_in[7];
    const float* imp   = (const float*)d_in[8];
    float* out = (float*)d_out;

    build_table_kernel<<<NTAB / 128, 128>>>(t_in, mus, nlg, mus_t, nlg_t, W, bias, imp);
    pair_kernel<<<PAIR_BLOCKS, PTPB>>>(x, out);
}

// round 11
// speedup vs baseline: 1.0019x; 1.0019x over previous
#include <cuda_runtime.h>
#include <math.h>

#define NP 512
#define ND 3
#define NK 32
#define NT 10
#define NB 8
#define EPSF 1e-6f

#define NTAB 512
#define DRANGE 4.0f
#define TSCALE ((float)NTAB / DRANGE)

#define IPB 16                           // target i's per block
#define PTPB (IPB * 32)                  // 512 threads
#define PAIR_BLOCKS (NB * (NP / IPB))    // 256 blocks

__device__ float    g_divpart[NB * NP];
__device__ unsigned g_count = 0;

__global__ void __launch_bounds__(PTPB) fused_kernel(
    const float* __restrict__ t_in,
    const float* __restrict__ x,
    const float* __restrict__ mus,
    const float* __restrict__ nlg,
    const float* __restrict__ mus_t,
    const float* __restrict__ nlg_t,
    const float* __restrict__ W,
    const float* __restrict__ bias,
    const float* __restrict__ imp,
    float* __restrict__ out)
{
    __shared__ float2 s_raw[NTAB + 1];   // raw (fm, dfm) samples
    __shared__ float4 s_tab[NTAB];       // (fm, dfm, dfm_slope... ) = (base.xy, slope.zw)
    __shared__ float4 s_pos[NP];         // positions, float4-padded
    __shared__ float  s_mu[NK], s_ig2[NK], s_w[NK];
    __shared__ float  s_cadd;
    __shared__ int    s_last;

    const int tid   = threadIdx.x;
    const int bid   = blockIdx.x;
    const int b     = bid >> 5;               // batch (bid / 32)
    const int ibase = (bid & 31) * IPB;       // i-chunk of 16
    const int warp  = tid >> 5;
    const int lane  = tid & 31;

    // ---- phase 1: position fill (issue global loads early) ----
    {
        const float* xb = x + b * (NP * ND) + tid * 3;
        float4 p;
        p.x = xb[0]; p.y = xb[1]; p.z = xb[2]; p.w = 0.f;
        s_pos[tid] = p;
    }

    // ---- phase 2 (warp 0 only): effective weights + constants ----
    if (tid < NK) {
        const int k = tid;
        const float t = t_in[0];
        float tr[NT];
        float ssum = 0.f;
#pragma unroll
        for (int q = 0; q < NT; q++) {
            float ig = __expf(nlg_t[q]);
            float df = t - mus_t[q];
            float v  = __expf(-df * df * ig * ig);
            tr[q] = v;
            ssum += v;
        }
        const float invs = 1.0f / (EPSF + ssum);

        float w = 0.f;
#pragma unroll
        for (int q = 0; q < NT; q++) w = fmaf(W[k * NT + q], tr[q], w);
        w *= invs;

        float v = imp[k] * imp[k] * w;
#pragma unroll
        for (int o = 16; o; o >>= 1) v += __shfl_down_sync(0xffffffffu, v, o);

        float ig = __expf(nlg[k]);
        s_mu[k]  = mus[k];
        s_ig2[k] = ig * ig;
        s_w[k]   = w;
        if (k == 0) {
            float cadd = v;
#pragma unroll
            for (int q = 0; q < NT; q++) cadd = fmaf(bias[q] * invs, tr[q], cadd);
            s_cadd = cadd;
        }
    }
    __syncthreads();

    // ---- phase 3: per-block table build (one entry per thread; thread 0 adds the +1 tail) ----
    {
        const float cadd = s_cadd;
#pragma unroll
        for (int h = 0; h < 2; h++) {
            const int idx = (h == 0) ? tid : NTAB;
            if (h == 1 && tid != 0) break;
            const float d = (float)idx * (DRANGE / (float)NTAB);
            float S0 = 0.f, W0 = 0.f, SD = 0.f, SDW = 0.f;
#pragma unroll 8
            for (int k = 0; k < NK; k++) {
                float diff = d - s_mu[k];
                float ig2  = s_ig2[k];
                float r  = __expf(-diff * diff * ig2);
                float dr = -2.f * diff * ig2 * r;
                S0  += r;
                W0   = fmaf(r,  s_w[k], W0);
                SD  += dr;
                SDW  = fmaf(dr, s_w[k], SDW);
            }
            const float inv = 1.0f / (EPSF + S0);
            float2 e;
            e.x = fmaf(W0, inv, cadd);          // fm
            e.y = (SDW - W0 * SD * inv) * inv;  // dfm
            s_raw[idx] = e;
        }
    }
    __syncthreads();

    // ---- phase 4: slope-form quads ----
    {
        const float2 e0 = s_raw[tid];
        const float2 e1 = s_raw[tid + 1];
        float4 q;
        q.x = e0.x; q.y = e0.y;
        q.z = e1.x - e0.x; q.w = e1.y - e0.y;
        s_tab[tid] = q;
    }
    __syncthreads();

    // ---- phase 5: pair loop (warp w -> target i) ----
    const int i = ibase + warp;
    const float4 pi = s_pos[i];

    float fx = 0.f, fy = 0.f, fz = 0.f, dv = 0.f;

#pragma unroll 8
    for (int it = 0; it < NP / 32; it++) {
        const int j = it * 32 + lane;
        const float4 pj = s_pos[j];
        const float rx = pi.x - pj.x;
        const float ry = pi.y - pj.y;
        const float rz = pi.z - pj.z;
        float d2s = fmaf(rx, rx, fmaf(ry, ry, fmaf(rz, rz, EPSF)));
        float d;
        asm("sqrt.approx.ftz.f32 %0, %1;" : "=f"(d) : "f"(d2s));

        float u = d * TSCALE;
        int i0 = (int)u;
        i0 = min(i0, NTAB - 1);
        float frac = u - (float)i0;
        const float4 q = s_tab[i0];
        float fm  = fmaf(frac, q.z, q.x);
        float dfm = fmaf(frac, q.w, q.y);

        if (j == i) { fm = 0.f; dfm = 0.f; }   // remove_diagonal

        fx = fmaf(rx, fm, fx);
        fy = fmaf(ry, fm, fy);
        fz = fmaf(rz, fm, fz);
        dv += fmaf(d, dfm, 3.f * fm);
    }

    // ---- warp reduction + output ----
    const unsigned m = 0xffffffffu;
#pragma unroll
    for (int o = 16; o; o >>= 1) {
        fx += __shfl_down_sync(m, fx, o);
        fy += __shfl_down_sync(m, fy, o);
        fz += __shfl_down_sync(m, fz, o);
        dv += __shfl_down_sync(m, dv, o);
    }
    if (lane == 0) {
        float* fo = out + b * (NP * ND) + i * 3;
        fo[0] = fx; fo[1] = fy; fo[2] = fz;
        g_divpart[b * NP + i] = dv;
        __threadfence();
    }
    __syncthreads();

    if (tid == 0) {
        unsigned old = atomicInc(&g_count, PAIR_BLOCKS - 1);
        s_last = (old == PAIR_BLOCKS - 1) ? 1 : 0;
    }
    __syncthreads();

    // ---- last block: deterministic divergence reduction ----
    if (s_last) {
        __threadfence();
        if (tid < 256) {
            const int bb = tid >> 5;   // warp -> batch (8 warps)
            const int l  = tid & 31;
            float v = 0.f;
#pragma unroll
            for (int c = 0; c < 16; c++)
                v += __ldcg(&g_divpart[bb * NP + l * 16 + c]);
#pragma unroll
            for (int o = 16; o; o >>= 1) v += __shfl_down_sync(m, v, o);
            if (l == 0) out[NB * NP * ND + bb] = -v;
        }
    }
}

extern "C" void kernel_launch(void* const* d_in, const int* in_sizes, int n_in,
                              void* d_out, int out_size)
{
    const float* t_in  = (const float*)d_in[0];
    const float* x     = (const float*)d_in[1];
    const float* mus   = (const float*)d_in[2];
    const float* nlg   = (const float*)d_in[3];
    const float* mus_t = (const float*)d_in[4];
    const float* nlg_t = (const float*)d_in[5];
    const float* W     = (const float*)d_in[6];
    const float* bias  = (const float*)d_in[7];
    const float* imp   = (const float*)d_in[8];
    float* out = (float*)d_out;

    fused_kernel<<<PAIR_BLOCKS, PTPB>>>(t_in, x, mus, nlg, mus_t, nlg_t, W, bias, imp, out);
}